// round 16
// baseline (speedup 1.0000x reference)
#include <cuda_runtime.h>
#include <cuda_bf16.h>
#include <cstdint>

// Shapes (fixed): B=1, C=8, O=8, G=12, X=Y=Z=12, H=8, W=40, Bb=7, 27 taps
// Phase 1 as HMMA GEMM (mma.sync bf16, plain-PTX — tcgen05 unavailable: harness
// builds via compute_103 virtual arch):
//   Y^T[320pix, 64] = X^T[320, 256pad] * W^T[256pad, 64],  k = f*8+c (K=216 used)
//   m16n8k16 tiles, 3-split bf16 (AhiBhi + AhiBlo + AloBhi) for fp32-grade accuracy.
// Phase 2 scalar (FFMA2): out[g*8+o] = biasSum[o] + sum basis[(g+border)%12]*Y[..]
// One CTA per cell (729), NT=320 (10 warps), ~116KB smem, 1 CTA/SM.
// Shell zeroing fully interleaved into the conversion loop. prep (PDL-overlapped)
// builds split-bf16 W^T images + pre-rotated basis.

#define NT 320

#define OFF_BP     0            // basis   2016 f = 8064 B
#define OFF_BIAS   8064         // 8 f
#define OFF_XT_HI  8096         // 320 rows x 72 bf16 (144B stride) = 46080 B
#define OFF_XT_LO  54176        // 46080 B
#define OFF_B_HI   100256       // 64 rows x 72 bf16 = 9216 B
#define OFF_B_LO   109472       // 9216 B
#define SMEM_BYTES 118688
#define OFF_SYT    8096         // sY^T [320][65] f32 = 83200 B, aliases XT after MMA

#define TOT_SLOTS (96 * 1728 * 80)
#define NTHREADS  (729 * NT)

typedef unsigned long long ull;

__device__ __forceinline__ void fma2(ull& d, ull a, ull b) {
    asm("fma.rn.f32x2 %0, %1, %2, %0;" : "+l"(d) : "l"(a), "l"(b));
}
__device__ __forceinline__ ull pack2(float lo, float hi) {
    ull r; asm("mov.b64 %0, {%1, %2};" : "=l"(r) : "f"(lo), "f"(hi)); return r;
}
__device__ __forceinline__ void unpack2(float& lo, float& hi, ull v) {
    asm("mov.b64 {%0, %1}, %2;" : "=f"(lo), "=f"(hi) : "l"(v));
}
__device__ __forceinline__ uint32_t smem_u32(const void* p) {
    uint32_t a;
    asm("{ .reg .u64 t; cvta.to.shared.u64 t, %1; cvt.u32.u64 %0, t; }" : "=r"(a) : "l"(p));
    return a;
}
__device__ __forceinline__ void mma16816(float* d, const uint32_t* a, const uint32_t* b) {
    asm volatile(
        "mma.sync.aligned.m16n8k16.row.col.f32.bf16.bf16.f32 "
        "{%0,%1,%2,%3}, {%4,%5,%6,%7}, {%8,%9}, {%0,%1,%2,%3};"
        : "+f"(d[0]), "+f"(d[1]), "+f"(d[2]), "+f"(d[3])
        : "r"(a[0]), "r"(a[1]), "r"(a[2]), "r"(a[3]), "r"(b[0]), "r"(b[1]));
}
__device__ __forceinline__ void ldsm_x4(uint32_t* r, uint32_t addr) {
    asm volatile("ldmatrix.sync.aligned.m8n8.x4.shared.b16 {%0,%1,%2,%3}, [%4];"
                 : "=r"(r[0]), "=r"(r[1]), "=r"(r[2]), "=r"(r[3]) : "r"(addr));
}
__device__ __forceinline__ void ldsm_x2t(uint32_t* r, uint32_t addr) {
    asm volatile("ldmatrix.sync.aligned.m8n8.x2.trans.shared.b16 {%0,%1}, [%2];"
                 : "=r"(r[0]), "=r"(r[1]) : "r"(addr));
}

// W^T split-bf16 images: [chunk q<4][k-row 64][72 cols bf16], cols 56..71 zero
__device__ __align__(16) __nv_bfloat16 gWThi[4 * 64 * 72];
__device__ __align__(16) __nv_bfloat16 gWTlo[4 * 64 * 72];
__device__ __align__(16) float gBp[2 * 63 * 16];
__device__ float gBiasS[8];

// One-shot prep. 37 blocks x 512.
__global__ __launch_bounds__(512)
void prep_kernel(const float* __restrict__ weight,
                 const float* __restrict__ bias,
                 const float* __restrict__ basis)
{
    const int blk = blockIdx.x, tid = threadIdx.x;
    if (blk < 36) {
        int idx = blk * 512 + tid;        // 0..18431
        int q   = idx / 4608;
        int r   = idx % 4608;
        int row = r / 72;                 // k-row within chunk
        int n   = r % 72;
        int fl = row >> 3, c = row & 7;
        int f  = q * 8 + fl;
        float val = 0.f;
        if (n < 56 && f < 27) {
            int o = n / 7, b = n % 7;
            val = weight[o * 1512 + c * 189 + f * 7 + b];
        }
        __nv_bfloat16 hi = __float2bfloat16(val);
        __nv_bfloat16 lo = __float2bfloat16(val - __bfloat162float(hi));
        gWThi[idx] = hi;
        gWTlo[idx] = lo;
    } else {
        if (tid < 8) {
            float s = 0.f;
            #pragma unroll
            for (int t = 0; t < 27; t++) s += bias[tid * 27 + t];
            gBiasS[tid] = s;
        }
        for (int i = tid; i < 2016; i += 512) {
            int s  = i / 1008;
            int kk = (i % 1008) >> 4;
            int g  = i & 15;
            int ge = g + s; if (ge >= 12) ge -= 12;
            gBp[i] = (g < 12) ? basis[ge * 63 + kk] : 0.f;
        }
    }
}

__global__ __launch_bounds__(NT, 1)
void gconv_main(const float* __restrict__ x, float* __restrict__ out)
{
    extern __shared__ char smemc[];
    float* smemf = reinterpret_cast<float*>(smemc);
    const uint32_t sb = smem_u32(smemc);
    const int tid  = threadIdx.x;
    const int wid  = tid >> 5;
    const int lane = tid & 31;
    const int cell = blockIdx.x;
    const int xi = cell / 81, yi = (cell / 9) % 9, zi = cell % 9;

    // ---- shell-zero iterator (pure arithmetic; PDL-independent) ----
    const int slot0 = cell * NT + tid;
    float4* zp = reinterpret_cast<float4*>(out) + slot0;
    int zcx, zcy; bool zcOut; int zkmax; int zk = 0;
    {
        int r   = slot0 % 138240;
        int cel = r / 80;
        zcx = cel / 144;
        int r2 = cel % 144;
        zcy = r2 / 12;
        int cz = r2 % 12;
        zcOut = (cz < 1) | (cz > 9);
        zkmax = (slot0 < TOT_SLOTS - 56 * NTHREADS) ? 57 : 56;
    }
    const float4 z4 = make_float4(0.f, 0.f, 0.f, 0.f);

#define SHELL_STEP()                                                        \
    {                                                                       \
        if (((unsigned)(zcx - 1) > 8u) | ((unsigned)(zcy - 1) > 8u) | zcOut)\
            *zp = z4;                                                       \
        zp += NTHREADS;                                                     \
        zcy += 3; zcx += 8;                                                 \
        if (zcy >= 12) { zcy -= 12; zcx++; }                                \
        if (zcx >= 12) zcx -= 12;                                           \
    }

    cudaGridDependencySynchronize();

    // ---- stage basis/bias ----
    float* sBp    = smemf + OFF_BP / 4;
    float* sBiasS = smemf + OFF_BIAS / 4;
    {
        float4* b4 = reinterpret_cast<float4*>(sBp);
        const float4* gb4 = reinterpret_cast<const float4*>(gBp);
        for (int i = tid; i < 504; i += NT) b4[i] = gb4[i];
        if (tid < 8) sBiasS[tid] = gBiasS[tid];
    }

    const float* xn = x + (size_t)xi * 46080 + (size_t)yi * 3840 + (size_t)zi * 320;

    // accumulators: 2 m-tiles x 8 n-tiles x 4
    float d[2][8][4];
    #pragma unroll
    for (int mt = 0; mt < 2; mt++)
        #pragma unroll
        for (int nt = 0; nt < 8; nt++)
            #pragma unroll
            for (int i = 0; i < 4; i++) d[mt][nt][i] = 0.f;

    const uint32_t xtHi = sb + OFF_XT_HI, xtLo = sb + OFF_XT_LO;
    const uint32_t bHi  = sb + OFF_B_HI,  bLo  = sb + OFF_B_LO;

    // ==== Phase 1: 4 K-chunks of 64 ====
    for (int q = 0; q < 4; q++) {
        // B chunk copy (1152 float4: hi then lo)
        {
            float4* dh = reinterpret_cast<float4*>(smemc + OFF_B_HI);
            float4* dl = reinterpret_cast<float4*>(smemc + OFF_B_LO);
            const float4* shh = reinterpret_cast<const float4*>(gWThi) + q * 576;
            const float4* sll = reinterpret_cast<const float4*>(gWTlo) + q * 576;
            for (int i = tid; i < 1152; i += NT) {
                if (i < 576) dh[i] = shh[i];
                else         dl[i - 576] = sll[i - 576];
            }
        }
        // X^T conversion: thread = pixel row; k = fl*8 + c, row stride 144B
        for (int fl = 0; fl < 8; fl++) {
            const int f = q * 8 + fl;
            float v[8];
            if (f < 27) {
                const float* xp = xn + (f / 9) * 46080 + ((f / 3) % 3) * 3840
                                     + (f % 3) * 320 + tid;
                #pragma unroll
                for (int c = 0; c < 8; c++) v[c] = xp[(size_t)c * 552960];
            } else {
                #pragma unroll
                for (int c = 0; c < 8; c++) v[c] = 0.f;
            }
            if (zk < zkmax) { SHELL_STEP(); } zk++;
            if (zk < zkmax) { SHELL_STEP(); } zk++;
            #pragma unroll
            for (int cp = 0; cp < 4; cp++) {
                float v0 = v[2 * cp], v1 = v[2 * cp + 1];
                __nv_bfloat16 h0 = __float2bfloat16(v0);
                __nv_bfloat16 h1 = __float2bfloat16(v1);
                __nv_bfloat16 l0 = __float2bfloat16(v0 - __bfloat162float(h0));
                __nv_bfloat16 l1 = __float2bfloat16(v1 - __bfloat162float(h1));
                __nv_bfloat162 ph; ph.x = h0; ph.y = h1;
                __nv_bfloat162 pl; pl.x = l0; pl.y = l1;
                const int off = tid * 144 + (fl * 8 + 2 * cp) * 2;
                *reinterpret_cast<__nv_bfloat162*>(smemc + OFF_XT_HI + off) = ph;
                *reinterpret_cast<__nv_bfloat162*>(smemc + OFF_XT_LO + off) = pl;
            }
        }
        __syncthreads();

        // MMA: per warp 2 m-tiles (pixels 32*wid..+31) x 8 n-tiles
        const int ksmax = (q < 3) ? 4 : 2;   // chunk 3: k-rows 32..63 all zero
        const int l16 = lane & 15;
        for (int ks = 0; ks < ksmax; ks++) {
            uint32_t ahi[2][4], alo[2][4];
            #pragma unroll
            for (int mt = 0; mt < 2; mt++) {
                const int prow = (wid * 2 + mt) * 16;
                uint32_t aoff = (uint32_t)(prow + l16) * 144 + ks * 32 + ((lane >> 4) << 4);
                ldsm_x4(ahi[mt], xtHi + aoff);
                ldsm_x4(alo[mt], xtLo + aoff);
            }
            #pragma unroll
            for (int nt = 0; nt < 8; nt++) {
                uint32_t bh[2], bl[2];
                uint32_t boff = (uint32_t)(ks * 16 + l16) * 144 + nt * 16;
                ldsm_x2t(bh, bHi + boff);
                ldsm_x2t(bl, bLo + boff);
                #pragma unroll
                for (int mt = 0; mt < 2; mt++) {
                    mma16816(d[mt][nt], ahi[mt], bh);
                    mma16816(d[mt][nt], ahi[mt], bl);
                    mma16816(d[mt][nt], alo[mt], bh);
                }
            }
        }
        __syncthreads();   // protect XT/B buffers before next chunk's conversion
    }

    // ---- remaining shell zeros (if any; zk already ran 64 guarded slots) ----
    while (zk < zkmax) { SHELL_STEP(); zk++; }

    // ==== store D frags to sY^T[pix][65] (aliases dead XT space) ====
    float* sYT = reinterpret_cast<float*>(smemc + OFF_SYT);
    {
        const int r0 = lane >> 2;
        const int c0 = (lane & 3) * 2;
        #pragma unroll
        for (int mt = 0; mt < 2; mt++) {
            const int prow = (wid * 2 + mt) * 16;
            #pragma unroll
            for (int nt = 0; nt < 8; nt++) {
                float* p0 = sYT + (prow + r0) * 65 + nt * 8 + c0;
                p0[0] = d[mt][nt][0];
                p0[1] = d[mt][nt][1];
                float* p1 = sYT + (prow + 8 + r0) * 65 + nt * 8 + c0;
                p1[0] = d[mt][nt][2];
                p1[1] = d[mt][nt][3];
            }
        }
    }
    __syncthreads();

    // ==== Phase 2: thread = pixel; two passes over o-halves ====
    const int h = tid / 40, w = tid % 40;
    const int hh0 = min(max(h, 1), 6) - 1;
    const int ww0 = min(max(w, 1), 38) - 1;
    const int bshift = ((h == 0) | (h == 7) | (w == 0) | (w == 39)) ? 1 : 0;
    const float* bas = sBp + bshift * 1008;

    for (int pass = 0; pass < 2; pass++) {
        ull accP[6][4];
        #pragma unroll
        for (int o = 0; o < 4; o++) {
            float bs = sBiasS[pass * 4 + o];
            ull bp = pack2(bs, bs);
            #pragma unroll
            for (int k = 0; k < 6; k++) accP[k][o] = bp;
        }

        const int mbase = pass * 28;
        for (int b = 0; b < 7; b++) {
            #pragma unroll
            for (int u = 0; u < 3; u++) {
                #pragma unroll
                for (int v = 0; v < 3; v++) {
                    const int kk = b * 9 + u * 3 + v;
                    const int yoff = (hh0 + u) * 40 + (ww0 + v);
                    const float* yr = sYT + yoff * 65 + mbase + b;
                    ull yd[4];
                    #pragma unroll
                    for (int o = 0; o < 4; o++) {
                        float yv = yr[o * 7];
                        yd[o] = pack2(yv, yv);
                    }
                    const ulonglong2* bp = reinterpret_cast<const ulonglong2*>(bas + kk * 16);
                    ulonglong2 b01 = bp[0];
                    ulonglong2 b23 = bp[1];
                    ulonglong2 b45 = bp[2];
                    #pragma unroll
                    for (int o = 0; o < 4; o++) {
                        fma2(accP[0][o], b01.x, yd[o]);
                        fma2(accP[1][o], b01.y, yd[o]);
                        fma2(accP[2][o], b23.x, yd[o]);
                        fma2(accP[3][o], b23.y, yd[o]);
                        fma2(accP[4][o], b45.x, yd[o]);
                        fma2(accP[5][o], b45.y, yd[o]);
                    }
                }
            }
        }

        float* ob = out + (size_t)(xi + 1) * 46080 + (size_t)(yi + 1) * 3840
                        + (size_t)(zi + 1) * 320 + tid + (size_t)pass * 4 * 552960;
        #pragma unroll
        for (int k = 0; k < 6; k++)
            #pragma unroll
            for (int o = 0; o < 4; o++) {
                float lo, hi;
                unpack2(lo, hi, accP[k][o]);
                ob[(size_t)((2 * k) * 8 + o) * 552960]     = lo;
                ob[(size_t)((2 * k + 1) * 8 + o) * 552960] = hi;
            }
    }
#undef SHELL_STEP
}

extern "C" void kernel_launch(void* const* d_in, const int* in_sizes, int n_in,
                              void* d_out, int out_size)
{
    const float* x      = (const float*)d_in[0];
    const float* weight = (const float*)d_in[1];
    const float* bias   = (const float*)d_in[2];
    const float* basis  = (const float*)d_in[3];
    // d_in[4..7] = I, J, T, bias_basis: deterministic clip/border maps, computed inline.
    float* out = (float*)d_out;

    cudaFuncSetAttribute(gconv_main, cudaFuncAttributeMaxDynamicSharedMemorySize, SMEM_BYTES);

    prep_kernel<<<37, 512>>>(weight, bias, basis);

    cudaLaunchConfig_t cfg = {};
    cfg.gridDim  = dim3(729, 1, 1);
    cfg.blockDim = dim3(NT, 1, 1);
    cfg.dynamicSmemBytes = SMEM_BYTES;
    cfg.stream = 0;
    cudaLaunchAttribute attr[1];
    attr[0].id = cudaLaunchAttributeProgrammaticStreamSerialization;
    attr[0].val.programmaticStreamSerializationAllowed = 1;
    cfg.attrs = attr;
    cfg.numAttrs = 1;
    cudaError_t e = cudaLaunchKernelEx(&cfg, gconv_main, x, out);
    if (e != cudaSuccess) {
        gconv_main<<<729, NT, SMEM_BYTES>>>(x, out);
    }
}

// round 17
// speedup vs baseline: 1.1257x; 1.1257x over previous
#include <cuda_runtime.h>
#include <cuda_bf16.h>
#include <cstdint>

// Shapes (fixed): B=1, C=8, O=8, G=12, X=Y=Z=12, H=8, W=40, Bb=7, 27 taps
// Phase 1 as HMMA GEMM (mma.sync bf16, plain PTX — tcgen05 unavailable under
// the harness's compute_103 virtual arch):
//   Y^T[320pix, 56] = X^T[320, 256pad] * W^T[256pad, 56],  k = f*8+c (K=216 used)
//   m16n8k16 tiles, 3-split bf16 (AhiBhi + AhiBlo + AloBhi) ~ fp32 accuracy.
// Phase 2 scalar FFMA2: out[g*8+o] = biasSum[o] + sum basis[(g+border)%12]*Y[..]
// One CTA per cell (729), NT=640 (20 warps, 1 m-tile each), ~116KB smem.
// Shell zeroing interleaved into the conversion loop. prep (PDL-overlapped).

#define NT 640

#define OFF_BP     0            // basis   2016 f = 8064 B
#define OFF_BIAS   8064         // 8 f (+pad)
#define OFF_XT_HI  8096         // 320 rows x 72 bf16 (144B stride) = 46080 B
#define OFF_XT_LO  54176        // 46080 B
#define OFF_B_HI   100256       // 64 rows x 72 bf16 = 9216 B
#define OFF_B_LO   109472       // 9216 B
#define SMEM_BYTES 118688
#define OFF_SYT    8096         // sY^T [320][65] f32 = 83200 B, aliases XT after MMA

#define TOT_SLOTS (96 * 1728 * 80)
#define NTHREADS  (729 * NT)    // 466560 = 3 go-channels + 648 cells
                                // 648 cells = +4 cx, +6 cy, +0 cz

typedef unsigned long long ull;

__device__ __forceinline__ void fma2(ull& d, ull a, ull b) {
    asm("fma.rn.f32x2 %0, %1, %2, %0;" : "+l"(d) : "l"(a), "l"(b));
}
__device__ __forceinline__ ull pack2(float lo, float hi) {
    ull r; asm("mov.b64 %0, {%1, %2};" : "=l"(r) : "f"(lo), "f"(hi)); return r;
}
__device__ __forceinline__ void unpack2(float& lo, float& hi, ull v) {
    asm("mov.b64 {%0, %1}, %2;" : "=f"(lo), "=f"(hi) : "l"(v));
}
__device__ __forceinline__ uint32_t smem_u32(const void* p) {
    uint32_t a;
    asm("{ .reg .u64 t; cvta.to.shared.u64 t, %1; cvt.u32.u64 %0, t; }" : "=r"(a) : "l"(p));
    return a;
}
__device__ __forceinline__ void mma16816(float* d, const uint32_t* a, const uint32_t* b) {
    asm volatile(
        "mma.sync.aligned.m16n8k16.row.col.f32.bf16.bf16.f32 "
        "{%0,%1,%2,%3}, {%4,%5,%6,%7}, {%8,%9}, {%0,%1,%2,%3};"
        : "+f"(d[0]), "+f"(d[1]), "+f"(d[2]), "+f"(d[3])
        : "r"(a[0]), "r"(a[1]), "r"(a[2]), "r"(a[3]), "r"(b[0]), "r"(b[1]));
}
__device__ __forceinline__ void ldsm_x4(uint32_t* r, uint32_t addr) {
    asm volatile("ldmatrix.sync.aligned.m8n8.x4.shared.b16 {%0,%1,%2,%3}, [%4];"
                 : "=r"(r[0]), "=r"(r[1]), "=r"(r[2]), "=r"(r[3]) : "r"(addr));
}
__device__ __forceinline__ void ldsm_x2t(uint32_t* r, uint32_t addr) {
    asm volatile("ldmatrix.sync.aligned.m8n8.x2.trans.shared.b16 {%0,%1}, [%2];"
                 : "=r"(r[0]), "=r"(r[1]) : "r"(addr));
}

// W^T split-bf16 images: [chunk q<4][k-row 64][72 cols bf16], cols 56..71 zero
__device__ __align__(16) __nv_bfloat16 gWThi[4 * 64 * 72];
__device__ __align__(16) __nv_bfloat16 gWTlo[4 * 64 * 72];
__device__ __align__(16) float gBp[2 * 63 * 16];
__device__ float gBiasS[8];

// One-shot prep. 37 blocks x 512.
__global__ __launch_bounds__(512)
void prep_kernel(const float* __restrict__ weight,
                 const float* __restrict__ bias,
                 const float* __restrict__ basis)
{
    const int blk = blockIdx.x, tid = threadIdx.x;
    if (blk < 36) {
        int idx = blk * 512 + tid;        // 0..18431
        int q   = idx / 4608;
        int r   = idx % 4608;
        int row = r / 72;                 // k-row within chunk
        int n   = r % 72;
        int fl = row >> 3, c = row & 7;
        int f  = q * 8 + fl;
        float val = 0.f;
        if (n < 56 && f < 27) {
            int o = n / 7, b = n % 7;
            val = weight[o * 1512 + c * 189 + f * 7 + b];
        }
        __nv_bfloat16 hi = __float2bfloat16(val);
        __nv_bfloat16 lo = __float2bfloat16(val - __bfloat162float(hi));
        gWThi[idx] = hi;
        gWTlo[idx] = lo;
    } else {
        if (tid < 8) {
            float s = 0.f;
            #pragma unroll
            for (int t = 0; t < 27; t++) s += bias[tid * 27 + t];
            gBiasS[tid] = s;
        }
        for (int i = tid; i < 2016; i += 512) {
            int s  = i / 1008;
            int kk = (i % 1008) >> 4;
            int g  = i & 15;
            int ge = g + s; if (ge >= 12) ge -= 12;
            gBp[i] = (g < 12) ? basis[ge * 63 + kk] : 0.f;
        }
    }
}

__global__ __launch_bounds__(NT, 1)
void gconv_main(const float* __restrict__ x, float* __restrict__ out)
{
    extern __shared__ char smemc[];
    float* smemf = reinterpret_cast<float*>(smemc);
    const uint32_t sb = smem_u32(smemc);
    const int tid  = threadIdx.x;
    const int wid  = tid >> 5;
    const int lane = tid & 31;
    const int cell = blockIdx.x;
    const int xi = cell / 81, yi = (cell / 9) % 9, zi = cell % 9;

    // conversion roles: pixel row + c-half
    const int px   = tid % 320;
    const int half = tid / 320;       // c in [half*4, half*4+4)

    // ---- shell-zero iterator (pure arithmetic; PDL-independent) ----
    const int slot0 = cell * NT + tid;
    float4* zp = reinterpret_cast<float4*>(out) + slot0;
    int zcx, zcy; bool zcOut; int zkmax; int zk = 0;
    {
        int r   = slot0 % 138240;
        int cel = r / 80;
        zcx = cel / 144;
        int r2 = cel % 144;
        zcy = r2 / 12;
        int cz = r2 % 12;
        zcOut = (cz < 1) | (cz > 9);
        zkmax = (slot0 < TOT_SLOTS - 28 * NTHREADS) ? 29 : 28;
    }
    const float4 z4 = make_float4(0.f, 0.f, 0.f, 0.f);

#define SHELL_STEP()                                                        \
    {                                                                       \
        if (((unsigned)(zcx - 1) > 8u) | ((unsigned)(zcy - 1) > 8u) | zcOut)\
            *zp = z4;                                                       \
        zp += NTHREADS;                                                     \
        zcy += 6; zcx += 4;                                                 \
        if (zcy >= 12) { zcy -= 12; zcx++; }                                \
        if (zcx >= 12) zcx -= 12;                                           \
    }

    cudaGridDependencySynchronize();

    // ---- stage basis/bias ----
    float* sBp    = smemf + OFF_BP / 4;
    float* sBiasS = smemf + OFF_BIAS / 4;
    {
        float4* b4 = reinterpret_cast<float4*>(sBp);
        const float4* gb4 = reinterpret_cast<const float4*>(gBp);
        for (int i = tid; i < 504; i += NT) b4[i] = gb4[i];
        if (tid < 8) sBiasS[tid] = gBiasS[tid];
    }

    const float* xn = x + (size_t)xi * 46080 + (size_t)yi * 3840 + (size_t)zi * 320;

    // accumulators: 1 m-tile x 7 n-tiles x 4
    float d[7][4];
    #pragma unroll
    for (int nt = 0; nt < 7; nt++)
        #pragma unroll
        for (int i = 0; i < 4; i++) d[nt][i] = 0.f;

    const uint32_t xtHi = sb + OFF_XT_HI, xtLo = sb + OFF_XT_LO;
    const uint32_t bHi  = sb + OFF_B_HI,  bLo  = sb + OFF_B_LO;

    // ==== Phase 1: 4 K-chunks of 64 ====
    for (int q = 0; q < 4; q++) {
        // B chunk copy (1152 float4: hi then lo)
        {
            float4* dh = reinterpret_cast<float4*>(smemc + OFF_B_HI);
            float4* dl = reinterpret_cast<float4*>(smemc + OFF_B_LO);
            const float4* shh = reinterpret_cast<const float4*>(gWThi) + q * 576;
            const float4* sll = reinterpret_cast<const float4*>(gWTlo) + q * 576;
            for (int i = tid; i < 1152; i += NT) {
                if (i < 576) dh[i] = shh[i];
                else         dl[i - 576] = sll[i - 576];
            }
        }
        // X^T conversion: thread = (pixel, c-half); k = fl*8 + c, row stride 144B
        for (int fl = 0; fl < 8; fl++) {
            const int f = q * 8 + fl;
            float v[4];
            if (f < 27) {
                const float* xp = xn + (f / 9) * 46080 + ((f / 3) % 3) * 3840
                                     + (f % 3) * 320 + px;
                #pragma unroll
                for (int j = 0; j < 4; j++)
                    v[j] = xp[(size_t)(half * 4 + j) * 552960];
            } else {
                #pragma unroll
                for (int j = 0; j < 4; j++) v[j] = 0.f;
            }
            if (zk < zkmax) { SHELL_STEP(); } zk++;
            #pragma unroll
            for (int cp = 0; cp < 2; cp++) {
                float v0 = v[2 * cp], v1 = v[2 * cp + 1];
                __nv_bfloat16 h0 = __float2bfloat16(v0);
                __nv_bfloat16 h1 = __float2bfloat16(v1);
                __nv_bfloat16 l0 = __float2bfloat16(v0 - __bfloat162float(h0));
                __nv_bfloat16 l1 = __float2bfloat16(v1 - __bfloat162float(h1));
                __nv_bfloat162 ph; ph.x = h0; ph.y = h1;
                __nv_bfloat162 pl; pl.x = l0; pl.y = l1;
                const int off = px * 144 + (fl * 8 + half * 4 + 2 * cp) * 2;
                *reinterpret_cast<__nv_bfloat162*>(smemc + OFF_XT_HI + off) = ph;
                *reinterpret_cast<__nv_bfloat162*>(smemc + OFF_XT_LO + off) = pl;
            }
        }
        __syncthreads();

        // MMA: warp w -> pixels 16w..16w+15 (m-tile), 7 n-tiles
        const int ksmax = (q < 3) ? 4 : 2;   // chunk 3: k-rows 32..63 all zero
        const int l16 = lane & 15;
        for (int ks = 0; ks < ksmax; ks++) {
            uint32_t ahi[4], alo[4];
            {
                uint32_t aoff = (uint32_t)(wid * 16 + l16) * 144 + ks * 32
                              + ((lane >> 4) << 4);
                ldsm_x4(ahi, xtHi + aoff);
                ldsm_x4(alo, xtLo + aoff);
            }
            #pragma unroll
            for (int nt = 0; nt < 7; nt++) {
                uint32_t bh[2], bl[2];
                uint32_t boff = (uint32_t)(ks * 16 + l16) * 144 + nt * 16;
                ldsm_x2t(bh, bHi + boff);
                ldsm_x2t(bl, bLo + boff);
                mma16816(d[nt], ahi, bh);
                mma16816(d[nt], ahi, bl);
                mma16816(d[nt], alo, bh);
            }
        }
        __syncthreads();   // protect XT/B buffers before next chunk's conversion
    }

    // ---- remaining shell zeros (32 loop slots >= zkmax, but keep safety) ----
    while (zk < zkmax) { SHELL_STEP(); zk++; }

    // ==== store D frags to sY^T[pix][65] (aliases dead XT space) ====
    float* sYT = reinterpret_cast<float*>(smemc + OFF_SYT);
    {
        const int r0 = lane >> 2;
        const int c0 = (lane & 3) * 2;
        const int prow = wid * 16;
        #pragma unroll
        for (int nt = 0; nt < 7; nt++) {
            float* p0 = sYT + (prow + r0) * 65 + nt * 8 + c0;
            p0[0] = d[nt][0];
            p0[1] = d[nt][1];
            float* p1 = sYT + (prow + 8 + r0) * 65 + nt * 8 + c0;
            p1[0] = d[nt][2];
            p1[1] = d[nt][3];
        }
    }
    __syncthreads();

    // ==== Phase 2: thread = (o-half oh, pixel); 12 g (6 FFMA2 pairs) x 4 o ====
    const int oh = half;               // o in [oh*4, oh*4+4)
    const int h = px / 40, w = px % 40;
    const int hh0 = min(max(h, 1), 6) - 1;
    const int ww0 = min(max(w, 1), 38) - 1;
    const int bshift = ((h == 0) | (h == 7) | (w == 0) | (w == 39)) ? 1 : 0;
    const float* bas = sBp + bshift * 1008;

    ull accP[6][4];
    #pragma unroll
    for (int o = 0; o < 4; o++) {
        float bs = sBiasS[oh * 4 + o];
        ull bp = pack2(bs, bs);
        #pragma unroll
        for (int k = 0; k < 6; k++) accP[k][o] = bp;
    }

    const int mbase = oh * 28;
    for (int b = 0; b < 7; b++) {
        #pragma unroll
        for (int u = 0; u < 3; u++) {
            #pragma unroll
            for (int v = 0; v < 3; v++) {
                const int kk = b * 9 + u * 3 + v;
                const int yoff = (hh0 + u) * 40 + (ww0 + v);
                const float* yr = sYT + yoff * 65 + mbase + b;
                ull yd[4];
                #pragma unroll
                for (int o = 0; o < 4; o++) {
                    float yv = yr[o * 7];
                    yd[o] = pack2(yv, yv);
                }
                const ulonglong2* bp = reinterpret_cast<const ulonglong2*>(bas + kk * 16);
                ulonglong2 b01 = bp[0];
                ulonglong2 b23 = bp[1];
                ulonglong2 b45 = bp[2];
                #pragma unroll
                for (int o = 0; o < 4; o++) {
                    fma2(accP[0][o], b01.x, yd[o]);
                    fma2(accP[1][o], b01.y, yd[o]);
                    fma2(accP[2][o], b23.x, yd[o]);
                    fma2(accP[3][o], b23.y, yd[o]);
                    fma2(accP[4][o], b45.x, yd[o]);
                    fma2(accP[5][o], b45.y, yd[o]);
                }
            }
        }
    }

    float* ob = out + (size_t)(xi + 1) * 46080 + (size_t)(yi + 1) * 3840
                    + (size_t)(zi + 1) * 320 + px + (size_t)oh * 4 * 552960;
    #pragma unroll
    for (int k = 0; k < 6; k++)
        #pragma unroll
        for (int o = 0; o < 4; o++) {
            float lo, hi;
            unpack2(lo, hi, accP[k][o]);
            ob[(size_t)((2 * k) * 8 + o) * 552960]     = lo;
            ob[(size_t)((2 * k + 1) * 8 + o) * 552960] = hi;
        }
#undef SHELL_STEP
}

extern "C" void kernel_launch(void* const* d_in, const int* in_sizes, int n_in,
                              void* d_out, int out_size)
{
    const float* x      = (const float*)d_in[0];
    const float* weight = (const float*)d_in[1];
    const float* bias   = (const float*)d_in[2];
    const float* basis  = (const float*)d_in[3];
    // d_in[4..7] = I, J, T, bias_basis: deterministic clip/border maps, computed inline.
    float* out = (float*)d_out;

    cudaFuncSetAttribute(gconv_main, cudaFuncAttributeMaxDynamicSharedMemorySize, SMEM_BYTES);

    prep_kernel<<<37, 512>>>(weight, bias, basis);

    cudaLaunchConfig_t cfg = {};
    cfg.gridDim  = dim3(729, 1, 1);
    cfg.blockDim = dim3(NT, 1, 1);
    cfg.dynamicSmemBytes = SMEM_BYTES;
    cfg.stream = 0;
    cudaLaunchAttribute attr[1];
    attr[0].id = cudaLaunchAttributeProgrammaticStreamSerialization;
    attr[0].val.programmaticStreamSerializationAllowed = 1;
    cfg.attrs = attr;
    cfg.numAttrs = 1;
    cudaError_t e = cudaLaunchKernelEx(&cfg, gconv_main, x, out);
    if (e != cudaSuccess) {
        gconv_main<<<729, NT, SMEM_BYTES>>>(x, out);
    }
}